// round 15
// baseline (speedup 1.0000x reference)
#include <cuda_runtime.h>
#include <cuda_fp16.h>
#include <math.h>
#include <stdint.h>

#define HDIM 128
#define MAXM 1000
#define MAXJ 5000
#define MAXN 200000
#define TILE_OPS 128

#define RCHUNK 2048
#define RTH1   512
#define MAXP   512

// ------------------------------ scratch ------------------------------------
__device__ __align__(16) float  g_part[16 * HDIM];   // 16 k-partials of g
__device__ __align__(16) __half g_Ah[MAXM * HDIM];   // fp16 A rows (incl. g)
__device__ __align__(16) __half g_Bh[MAXJ * HDIM];   // fp16 B rows
__device__ __align__(16) float  g_scores[MAXN];
__device__ float  g_pmax[MAXP];
__device__ int    g_pidx[MAXP];
__device__ double g_pZ[MAXP];
__device__ double g_pS1[MAXP];
__device__ unsigned int g_rcount;                    // last-block ticket (self-resetting)
// W1^T (rows = output h, cols = k), fp16, blocked-SW128 layout (32KB).
__device__ __align__(16) unsigned char g_W1T[32768];

// --------------------------- helpers ---------------------------------------
__device__ __forceinline__ uint32_t smem_u32(const void* p) {
    uint32_t a;
    asm("{ .reg .u64 t; cvta.to.shared.u64 t, %1; cvt.u32.u64 %0, t; }"
        : "=r"(a) : "l"(p));
    return a;
}

// swizzled byte offset in a 128row x 128col fp16 blocked-SW128 tile
__device__ __forceinline__ uint32_t tile_off(int row, int col) {
    uint32_t off = (uint32_t)(((row >> 3) + ((col >> 6) << 4)) * 1024
                              + (row & 7) * 128 + (col & 63) * 2);
    return off ^ ((off >> 3) & 0x70);
}

__device__ __forceinline__ void ldsm4(uint32_t* r, uint32_t addr) {
    asm volatile("ldmatrix.sync.aligned.m8n8.x4.shared.b16 {%0,%1,%2,%3}, [%4];"
                 : "=r"(r[0]), "=r"(r[1]), "=r"(r[2]), "=r"(r[3]) : "r"(addr));
}
__device__ __forceinline__ void mma_f16(float* d, const uint32_t* a,
                                        uint32_t b0, uint32_t b1) {
    asm volatile("mma.sync.aligned.m16n8k16.row.col.f32.f16.f16.f32 "
                 "{%0,%1,%2,%3}, {%4,%5,%6,%7}, {%8,%9}, {%0,%1,%2,%3};"
                 : "+f"(d[0]), "+f"(d[1]), "+f"(d[2]), "+f"(d[3])
                 : "r"(a[0]), "r"(a[1]), "r"(a[2]), "r"(a[3]), "r"(b0), "r"(b1));
}

// warp argmax merge step
__device__ __forceinline__ void wmerge(float& v, int& bi, unsigned mask, int off) {
    float vo = __shfl_xor_sync(mask, v, off);
    int io = __shfl_xor_sync(mask, bi, off);
    if (vo > v || (vo == v && io < bi)) { v = vo; bi = io; }
}

// ---------------------------------------------------------------------------
// Kernel P1: parallel prep stage 1 (R12, proven).
// ---------------------------------------------------------------------------
__global__ void __launch_bounds__(HDIM)
kern_prep1(const float* __restrict__ x_graph,
           const float* __restrict__ W0,
           const float* __restrict__ b0,
           const float* __restrict__ W1)
{
    int h = threadIdx.x;
    int r = blockIdx.x;
    if (r < 16) {
        __shared__ float xs[16];
        if (h < 16) xs[h] = x_graph[r * 16 + h];
        __syncthreads();
        float acc = (r == 0) ? b0[h] : 0.0f;
        #pragma unroll
        for (int k = 0; k < 16; ++k)
            acc = fmaf(xs[k], W0[(r * 16 + k) * HDIM + h], acc);
        g_part[r * HDIM + h] = acc;
    } else {
        int wb = r - 16;
        int idx = wb * HDIM + h;
        int rr = idx >> 7;
        int cc = idx & 127;
        float w = W1[cc * HDIM + rr];
        *(__half*)(g_W1T + tile_off(rr, cc)) = __float2half(w);
    }
}

// ---------------------------------------------------------------------------
// Kernel P2: A/B rows, 8 rows per block, 128 threads (R12, proven).
// ---------------------------------------------------------------------------
__global__ void __launch_bounds__(HDIM)
kern_AB8(const float* __restrict__ x_m,
         const float* __restrict__ x_job,
         const float* __restrict__ W0,
         int M, int J, int ablocks)
{
    __shared__ __align__(16) float xsT[HDIM][8];
    int tid = threadIdx.x;
    int b = blockIdx.x;

    bool isA = (b < ablocks);
    int row0   = isA ? b * 8 : (b - ablocks) * 8;
    int nrows  = isA ? min(8, M - row0) : min(8, J - row0);
    const float* src = isA ? (x_m + (size_t)row0 * HDIM)
                           : (x_job + (size_t)row0 * HDIM);
    const float* w   = W0 + (size_t)((isA ? 2 : 3) * HDIM) * HDIM;
    __half* dst = (isA ? g_Ah : g_Bh) + (size_t)row0 * HDIM;

    {
        int i = tid >> 4;
        int c0 = (tid & 15) * 8;
        if (i < nrows) {
            float4 v0 = *(const float4*)(src + i * HDIM + c0);
            float4 v1 = *(const float4*)(src + i * HDIM + c0 + 4);
            xsT[c0 + 0][i] = v0.x; xsT[c0 + 1][i] = v0.y;
            xsT[c0 + 2][i] = v0.z; xsT[c0 + 3][i] = v0.w;
            xsT[c0 + 4][i] = v1.x; xsT[c0 + 5][i] = v1.y;
            xsT[c0 + 6][i] = v1.z; xsT[c0 + 7][i] = v1.w;
        } else {
            #pragma unroll
            for (int q = 0; q < 8; ++q) xsT[c0 + q][i] = 0.0f;
        }
    }
    __syncthreads();

    int h = tid;
    float acc[8];
    float ginit = 0.0f;
    if (isA) {
        #pragma unroll
        for (int p = 0; p < 16; ++p) ginit += g_part[p * HDIM + h];
    }
    #pragma unroll
    for (int i = 0; i < 8; ++i) acc[i] = ginit;

    #pragma unroll 4
    for (int k = 0; k < HDIM; ++k) {
        float wv = w[k * HDIM + h];
        const float4* xr = (const float4*)&xsT[k][0];
        float4 x0 = xr[0], x1 = xr[1];
        acc[0] = fmaf(x0.x, wv, acc[0]);
        acc[1] = fmaf(x0.y, wv, acc[1]);
        acc[2] = fmaf(x0.z, wv, acc[2]);
        acc[3] = fmaf(x0.w, wv, acc[3]);
        acc[4] = fmaf(x1.x, wv, acc[4]);
        acc[5] = fmaf(x1.y, wv, acc[5]);
        acc[6] = fmaf(x1.z, wv, acc[6]);
        acc[7] = fmaf(x1.w, wv, acc[7]);
    }
    #pragma unroll
    for (int i = 0; i < 8; ++i)
        if (i < nrows) dst[i * HDIM + h] = __float2half(acc[i]);
}

// ---------------------------------------------------------------------------
// Kernel 2: fp16 HMMA tile kernel — R7 layout, software-pipelined mainloop.
// ---------------------------------------------------------------------------
#define OFF_A     0
#define OFF_W     32768
#define OFF_SB1   65536
#define OFF_SW2   66048
#define SMEM_TILE_TOTAL 66560

__global__ void __launch_bounds__(256, 2)
kern_tile(const int* __restrict__ m_ids,
          const int* __restrict__ job_idx,
          const float* __restrict__ b1,
          const float* __restrict__ W2,
          const float* __restrict__ b2,
          int n)
{
    extern __shared__ char smem[];
    uint32_t sb = smem_u32(smem);
    int tid = threadIdx.x;
    int wid = tid >> 5;
    int lid = tid & 31;
    int base = blockIdx.x * TILE_OPS;

    {
        const uint4* src = (const uint4*)g_W1T;
        uint4* dst = (uint4*)(smem + OFF_W);
        #pragma unroll
        for (int i = 0; i < 8; ++i)
            dst[tid + 256 * i] = src[tid + 256 * i];
    }
    if (tid < HDIM) {
        ((float*)(smem + OFF_SB1))[tid] = b1[tid];
        ((float*)(smem + OFF_SW2))[tid] = W2[tid];
    }

    {
        int c0 = lid * 4;
        uint32_t colpart = (uint32_t)(((c0 >> 6) << 4) * 1024 + (c0 & 63) * 2);
        #pragma unroll 4
        for (int i = 0; i < 16; ++i) {
            int t = wid * 16 + i;
            int op = base + t;
            int m = 0, j = 0;
            if (op < n) { m = m_ids[op]; j = job_idx[op]; }
            uint2 ua = *(const uint2*)(g_Ah + m * HDIM + c0);
            uint2 ub = *(const uint2*)(g_Bh + j * HDIM + c0);
            float2 a0 = __half22float2(*(const half2*)&ua.x);
            float2 a1 = __half22float2(*(const half2*)&ua.y);
            float2 b0f = __half22float2(*(const half2*)&ub.x);
            float2 b1f = __half22float2(*(const half2*)&ub.y);
            float v0 = fmaxf(a0.x + b0f.x, 0.0f);
            float v1 = fmaxf(a0.y + b0f.y, 0.0f);
            float v2 = fmaxf(a1.x + b1f.x, 0.0f);
            float v3 = fmaxf(a1.y + b1f.y, 0.0f);
            half2 r0 = __floats2half2_rn(v0, v1);
            half2 r1 = __floats2half2_rn(v2, v3);
            uint32_t off = colpart + (uint32_t)(((t >> 3) << 10) + (t & 7) * 128);
            uint32_t sw = off ^ ((off >> 3) & 0x70);
            uint2 pv;
            pv.x = *(const uint32_t*)&r0;
            pv.y = *(const uint32_t*)&r1;
            *(uint2*)(smem + OFF_A + sw) = pv;
        }
    }
    __syncthreads();

    float d[16][4];
    #pragma unroll
    for (int nc = 0; nc < 16; ++nc)
        #pragma unroll
        for (int q = 0; q < 4; ++q) d[nc][q] = 0.0f;

    int arow = wid * 16 + (lid & 15);
    int acolh = (lid >> 4) * 8;
    int brow_in = ((lid >> 4) << 3) + (lid & 7);
    int bcol = ((lid >> 3) & 1) * 8;

    // ---- software-pipelined mainloop (same frag mapping as R7) ----
    {
        uint32_t a_cur[4], a_nxt[4], b_cur[4], b_nxt[4];
        ldsm4(a_cur, sb + OFF_A + tile_off(arow, 0 * 16 + acolh));
        ldsm4(b_cur, sb + OFF_W + tile_off(0 * 16 + brow_in, 0 * 16 + bcol));
        #pragma unroll
        for (int kc = 0; kc < 8; ++kc) {
            int kbase = kc * 16;
            #pragma unroll
            for (int np = 0; np < 8; ++np) {
                // prefetch next B frag (and next A at np==0)
                if (np < 7) {
                    ldsm4(b_nxt, sb + OFF_W +
                          tile_off((np + 1) * 16 + brow_in, kbase + bcol));
                } else if (kc < 7) {
                    ldsm4(b_nxt, sb + OFF_W +
                          tile_off(0 * 16 + brow_in, (kc + 1) * 16 + bcol));
                }
                if (np == 0 && kc < 7) {
                    ldsm4(a_nxt, sb + OFF_A +
                          tile_off(arow, (kc + 1) * 16 + acolh));
                }
                mma_f16(d[2 * np],     a_cur, b_cur[0], b_cur[1]);
                mma_f16(d[2 * np + 1], a_cur, b_cur[2], b_cur[3]);
                #pragma unroll
                for (int q = 0; q < 4; ++q) b_cur[q] = b_nxt[q];
            }
            #pragma unroll
            for (int q = 0; q < 4; ++q) a_cur[q] = a_nxt[q];
        }
    }

    {
        const float* sb1 = (const float*)(smem + OFF_SB1);
        const float* sw2 = (const float*)(smem + OFF_SW2);
        int g = lid >> 2;
        int t4 = lid & 3;
        float s0 = 0.0f, s1 = 0.0f;
        #pragma unroll
        for (int nc = 0; nc < 16; ++nc) {
            int c0 = nc * 8 + 2 * t4;
            float bb0 = sb1[c0], bb1 = sb1[c0 + 1];
            float w0 = sw2[c0], w1 = sw2[c0 + 1];
            s0 = fmaf(fmaxf(d[nc][0] + bb0, 0.0f), w0, s0);
            s0 = fmaf(fmaxf(d[nc][1] + bb1, 0.0f), w1, s0);
            s1 = fmaf(fmaxf(d[nc][2] + bb0, 0.0f), w0, s1);
            s1 = fmaf(fmaxf(d[nc][3] + bb1, 0.0f), w1, s1);
        }
        unsigned mask = 0xffffffffu;
        s0 += __shfl_xor_sync(mask, s0, 1);
        s0 += __shfl_xor_sync(mask, s0, 2);
        s1 += __shfl_xor_sync(mask, s1, 1);
        s1 += __shfl_xor_sync(mask, s1, 2);
        if (t4 == 0) {
            float bias = b2[0];
            int op0 = base + wid * 16 + g;
            int op1 = op0 + 8;
            if (op0 < n) g_scores[op0] = s0 + bias;
            if (op1 < n) g_scores[op1] = s1 + bias;
        }
    }
}

// ---------------------------------------------------------------------------
// Kernel 3: fused softmax reduction.  Per-block partial (shuffle-based),
// then last-arriving block merges all partials in fixed index order and
// resets the ticket (deterministic, graph-replay-safe).
// ---------------------------------------------------------------------------
__global__ void __launch_bounds__(RTH1)
kern_reduce(int n, int nblk, float* __restrict__ out)
{
    __shared__ float  wv_s[16];
    __shared__ int    wi_s[16];
    __shared__ double wz_s[16];
    __shared__ double ws_s[16];
    __shared__ float  mx_s;
    __shared__ int    idx_s;
    __shared__ int    last_s;

    int tid = threadIdx.x;
    int lid = tid & 31;
    int wrp = tid >> 5;
    int b = blockIdx.x;
    int i0 = b * RCHUNK + tid * 4;
    unsigned mask = 0xffffffffu;

    float v[4] = { -INFINITY, -INFINITY, -INFINITY, -INFINITY };
    if (i0 + 3 < n) {
        float4 q = *(const float4*)(g_scores + i0);
        v[0] = q.x; v[1] = q.y; v[2] = q.z; v[3] = q.w;
    } else {
        #pragma unroll
        for (int q = 0; q < 4; ++q)
            if (i0 + q < n) v[q] = g_scores[i0 + q];
    }

    float best = v[0]; int bi = i0;
    #pragma unroll
    for (int q = 1; q < 4; ++q)
        if (v[q] > best) { best = v[q]; bi = i0 + q; }
    if (!(best > -INFINITY)) bi = 0x7fffffff;

    wmerge(best, bi, mask, 16);
    wmerge(best, bi, mask, 8);
    wmerge(best, bi, mask, 4);
    wmerge(best, bi, mask, 2);
    wmerge(best, bi, mask, 1);
    if (lid == 0) { wv_s[wrp] = best; wi_s[wrp] = bi; }
    __syncthreads();

    if (wrp == 0) {
        float vv = (lid < 16) ? wv_s[lid] : -INFINITY;
        int ii = (lid < 16) ? wi_s[lid] : 0x7fffffff;
        wmerge(vv, ii, mask, 8);
        wmerge(vv, ii, mask, 4);
        wmerge(vv, ii, mask, 2);
        wmerge(vv, ii, mask, 1);
        if (lid == 0) { mx_s = vv; idx_s = ii; }
    }
    __syncthreads();
    float mx = mx_s;

    double z = 0.0, s1d = 0.0;
    #pragma unroll
    for (int q = 0; q < 4; ++q) {
        if (v[q] > -INFINITY) {
            float t = v[q] - mx;
            float e = expf(t);
            z += (double)e;
            s1d += (double)t * (double)e;
        }
    }
    #pragma unroll
    for (int off = 16; off > 0; off >>= 1) {
        z   += __shfl_xor_sync(mask, z, off);
        s1d += __shfl_xor_sync(mask, s1d, off);
    }
    if (lid == 0) { wz_s[wrp] = z; ws_s[wrp] = s1d; }
    __syncthreads();

    if (wrp == 0) {
        double zz = (lid < 16) ? wz_s[lid] : 0.0;
        double ssv = (lid < 16) ? ws_s[lid] : 0.0;
        #pragma unroll
        for (int off = 8; off > 0; off >>= 1) {
            zz  += __shfl_xor_sync(mask, zz, off);
            ssv += __shfl_xor_sync(mask, ssv, off);
        }
        if (lid == 0) {
            g_pmax[b] = mx_s;
            g_pidx[b] = idx_s;
            g_pZ[b]   = zz;
            g_pS1[b]  = ssv;
        }
    }
    __syncthreads();

    // ---- last-block-done merge ----
    __threadfence();
    if (tid == 0) {
        unsigned int t = atomicAdd(&g_rcount, 1u);
        last_s = (t == (unsigned int)(nblk - 1)) ? 1 : 0;
    }
    __syncthreads();
    if (!last_s) return;

    // this block is last: all partials are visible (threadfence + atomic order)
    {
        float bb = (tid < nblk) ? g_pmax[tid] : -INFINITY;
        int ii = (tid < nblk) ? g_pidx[tid] : 0x7fffffff;
        wmerge(bb, ii, mask, 16);
        wmerge(bb, ii, mask, 8);
        wmerge(bb, ii, mask, 4);
        wmerge(bb, ii, mask, 2);
        wmerge(bb, ii, mask, 1);
        if (lid == 0) { wv_s[wrp] = bb; wi_s[wrp] = ii; }
        __syncthreads();
        if (wrp == 0) {
            float vv = (lid < 16) ? wv_s[lid] : -INFINITY;
            int ii2 = (lid < 16) ? wi_s[lid] : 0x7fffffff;
            wmerge(vv, ii2, mask, 8);
            wmerge(vv, ii2, mask, 4);
            wmerge(vv, ii2, mask, 2);
            wmerge(vv, ii2, mask, 1);
            if (lid == 0) { mx_s = vv; idx_s = ii2; }
        }
        __syncthreads();
        float gm = mx_s;

        double zc = 0.0, sc = 0.0;
        if (tid < nblk) {
            double zb = g_pZ[tid];
            if (zb > 0.0) {
                double dd = (double)g_pmax[tid] - (double)gm;
                double w = exp(dd);
                zc = w * zb;
                sc = w * (g_pS1[tid] + dd * zb);
            }
        }
        #pragma unroll
        for (int off = 16; off > 0; off >>= 1) {
            zc += __shfl_xor_sync(mask, zc, off);
            sc += __shfl_xor_sync(mask, sc, off);
        }
        if (lid == 0) { wz_s[wrp] = zc; ws_s[wrp] = sc; }
        __syncthreads();

        if (tid == 0) {
            double Z = 0.0, S1 = 0.0;
            #pragma unroll
            for (int wq = 0; wq < 16; ++wq) { Z += wz_s[wq]; S1 += ws_s[wq]; }
            double logZ = log(Z);
            out[0] = (float)idx_s;
            out[1] = (float)(1.0 / Z);
            out[2] = (float)(-logZ);
            out[3] = (float)(logZ - S1 / Z);
            g_rcount = 0;                     // reset for next graph replay
        }
    }
}

// ---------------------------------------------------------------------------
extern "C" void kernel_launch(void* const* d_in, const int* in_sizes, int n_in,
                              void* d_out, int out_size)
{
    const float* x_graph = (const float*)d_in[0];
    const float* x_m     = (const float*)d_in[1];
    const float* x_job   = (const float*)d_in[2];
    const int*   m_ids   = (const int*)  d_in[3];
    const int*   job_idx = (const int*)  d_in[4];
    const float* W0      = (const float*)d_in[5];
    const float* b0      = (const float*)d_in[6];
    const float* W1      = (const float*)d_in[7];
    const float* b1      = (const float*)d_in[8];
    const float* W2      = (const float*)d_in[9];
    const float* b2      = (const float*)d_in[10];

    int n = in_sizes[3];
    int M = in_sizes[1] / HDIM;
    int J = in_sizes[2] / HDIM;
    int tiles = (n + TILE_OPS - 1) / TILE_OPS;
    int rblks = (n + RCHUNK - 1) / RCHUNK;
    int ablocks = (M + 7) / 8;
    int bblocks = (J + 7) / 8;

    cudaFuncSetAttribute(kern_tile, cudaFuncAttributeMaxDynamicSharedMemorySize,
                         SMEM_TILE_TOTAL);

    kern_prep1<<<144, HDIM>>>(x_graph, W0, b0, W1);
    kern_AB8<<<ablocks + bblocks, HDIM>>>(x_m, x_job, W0, M, J, ablocks);
    kern_tile<<<tiles, 256, SMEM_TILE_TOTAL>>>(m_ids, job_idx, b1, W2, b2, n);
    kern_reduce<<<rblks, RTH1>>>(n, rblks, (float*)d_out);
}

// round 16
// speedup vs baseline: 1.0218x; 1.0218x over previous
#include <cuda_runtime.h>
#include <cuda_fp16.h>
#include <math.h>
#include <stdint.h>

#define HDIM 128
#define MAXM 1000
#define MAXJ 5000
#define MAXN 200000
#define TILE_OPS 128

#define RCHUNK 2048
#define RTH1   512
#define MAXP   512
#define RTH2   128

// ------------------------------ scratch ------------------------------------
__device__ __align__(16) float  g_part[16 * HDIM];   // 16 k-partials of g
__device__ __align__(16) __half g_Ah[MAXM * HDIM];   // fp16 A rows (incl. g)
__device__ __align__(16) __half g_Bh[MAXJ * HDIM];   // fp16 B rows
__device__ __align__(16) float  g_scores[MAXN];
__device__ float  g_pmax[MAXP];
__device__ int    g_pidx[MAXP];
__device__ double g_pZ[MAXP];
__device__ double g_pS1[MAXP];
// W1^T (rows = output h, cols = k), fp16, blocked-SW128 layout (32KB).
__device__ __align__(16) unsigned char g_W1T[32768];

// --------------------------- helpers ---------------------------------------
__device__ __forceinline__ uint32_t smem_u32(const void* p) {
    uint32_t a;
    asm("{ .reg .u64 t; cvta.to.shared.u64 t, %1; cvt.u32.u64 %0, t; }"
        : "=r"(a) : "l"(p));
    return a;
}

// swizzled byte offset in a 128row x 128col fp16 blocked-SW128 tile
__device__ __forceinline__ uint32_t tile_off(int row, int col) {
    uint32_t off = (uint32_t)(((row >> 3) + ((col >> 6) << 4)) * 1024
                              + (row & 7) * 128 + (col & 63) * 2);
    return off ^ ((off >> 3) & 0x70);
}

__device__ __forceinline__ void ldsm4(uint32_t* r, uint32_t addr) {
    asm volatile("ldmatrix.sync.aligned.m8n8.x4.shared.b16 {%0,%1,%2,%3}, [%4];"
                 : "=r"(r[0]), "=r"(r[1]), "=r"(r[2]), "=r"(r[3]) : "r"(addr));
}
__device__ __forceinline__ void mma_f16(float* d, const uint32_t* a,
                                        uint32_t b0, uint32_t b1) {
    asm volatile("mma.sync.aligned.m16n8k16.row.col.f32.f16.f16.f32 "
                 "{%0,%1,%2,%3}, {%4,%5,%6,%7}, {%8,%9}, {%0,%1,%2,%3};"
                 : "+f"(d[0]), "+f"(d[1]), "+f"(d[2]), "+f"(d[3])
                 : "r"(a[0]), "r"(a[1]), "r"(a[2]), "r"(a[3]), "r"(b0), "r"(b1));
}

// warp argmax merge step
__device__ __forceinline__ void wmerge(float& v, int& bi, unsigned mask, int off) {
    float vo = __shfl_xor_sync(mask, v, off);
    int io = __shfl_xor_sync(mask, bi, off);
    if (vo > v || (vo == v && io < bi)) { v = vo; bi = io; }
}

// ---------------------------------------------------------------------------
// Kernel P1: parallel prep stage 1 (R12, proven).
// ---------------------------------------------------------------------------
__global__ void __launch_bounds__(HDIM)
kern_prep1(const float* __restrict__ x_graph,
           const float* __restrict__ W0,
           const float* __restrict__ b0,
           const float* __restrict__ W1)
{
    int h = threadIdx.x;
    int r = blockIdx.x;
    if (r < 16) {
        __shared__ float xs[16];
        if (h < 16) xs[h] = x_graph[r * 16 + h];
        __syncthreads();
        float acc = (r == 0) ? b0[h] : 0.0f;
        #pragma unroll
        for (int k = 0; k < 16; ++k)
            acc = fmaf(xs[k], W0[(r * 16 + k) * HDIM + h], acc);
        g_part[r * HDIM + h] = acc;
    } else {
        int wb = r - 16;
        int idx = wb * HDIM + h;
        int rr = idx >> 7;
        int cc = idx & 127;
        float w = W1[cc * HDIM + rr];
        *(__half*)(g_W1T + tile_off(rr, cc)) = __float2half(w);
    }
}

// ---------------------------------------------------------------------------
// Kernel P2: A/B rows, 8 rows per block, 128 threads (R12, proven).
// ---------------------------------------------------------------------------
__global__ void __launch_bounds__(HDIM)
kern_AB8(const float* __restrict__ x_m,
         const float* __restrict__ x_job,
         const float* __restrict__ W0,
         int M, int J, int ablocks)
{
    __shared__ __align__(16) float xsT[HDIM][8];
    int tid = threadIdx.x;
    int b = blockIdx.x;

    bool isA = (b < ablocks);
    int row0   = isA ? b * 8 : (b - ablocks) * 8;
    int nrows  = isA ? min(8, M - row0) : min(8, J - row0);
    const float* src = isA ? (x_m + (size_t)row0 * HDIM)
                           : (x_job + (size_t)row0 * HDIM);
    const float* w   = W0 + (size_t)((isA ? 2 : 3) * HDIM) * HDIM;
    __half* dst = (isA ? g_Ah : g_Bh) + (size_t)row0 * HDIM;

    {
        int i = tid >> 4;
        int c0 = (tid & 15) * 8;
        if (i < nrows) {
            float4 v0 = *(const float4*)(src + i * HDIM + c0);
            float4 v1 = *(const float4*)(src + i * HDIM + c0 + 4);
            xsT[c0 + 0][i] = v0.x; xsT[c0 + 1][i] = v0.y;
            xsT[c0 + 2][i] = v0.z; xsT[c0 + 3][i] = v0.w;
            xsT[c0 + 4][i] = v1.x; xsT[c0 + 5][i] = v1.y;
            xsT[c0 + 6][i] = v1.z; xsT[c0 + 7][i] = v1.w;
        } else {
            #pragma unroll
            for (int q = 0; q < 8; ++q) xsT[c0 + q][i] = 0.0f;
        }
    }
    __syncthreads();

    int h = tid;
    float acc[8];
    float ginit = 0.0f;
    if (isA) {
        #pragma unroll
        for (int p = 0; p < 16; ++p) ginit += g_part[p * HDIM + h];
    }
    #pragma unroll
    for (int i = 0; i < 8; ++i) acc[i] = ginit;

    #pragma unroll 4
    for (int k = 0; k < HDIM; ++k) {
        float wv = w[k * HDIM + h];
        const float4* xr = (const float4*)&xsT[k][0];
        float4 x0 = xr[0], x1 = xr[1];
        acc[0] = fmaf(x0.x, wv, acc[0]);
        acc[1] = fmaf(x0.y, wv, acc[1]);
        acc[2] = fmaf(x0.z, wv, acc[2]);
        acc[3] = fmaf(x0.w, wv, acc[3]);
        acc[4] = fmaf(x1.x, wv, acc[4]);
        acc[5] = fmaf(x1.y, wv, acc[5]);
        acc[6] = fmaf(x1.z, wv, acc[6]);
        acc[7] = fmaf(x1.w, wv, acc[7]);
    }
    #pragma unroll
    for (int i = 0; i < 8; ++i)
        if (i < nrows) dst[i * HDIM + h] = __float2half(acc[i]);
}

// ---------------------------------------------------------------------------
// Kernel 2: fp16 HMMA tile kernel — R7 layout, software-pipelined mainloop
// (R13/R15 version, kept).
// ---------------------------------------------------------------------------
#define OFF_A     0
#define OFF_W     32768
#define OFF_SB1   65536
#define OFF_SW2   66048
#define SMEM_TILE_TOTAL 66560

__global__ void __launch_bounds__(256, 2)
kern_tile(const int* __restrict__ m_ids,
          const int* __restrict__ job_idx,
          const float* __restrict__ b1,
          const float* __restrict__ W2,
          const float* __restrict__ b2,
          int n)
{
    extern __shared__ char smem[];
    uint32_t sb = smem_u32(smem);
    int tid = threadIdx.x;
    int wid = tid >> 5;
    int lid = tid & 31;
    int base = blockIdx.x * TILE_OPS;

    {
        const uint4* src = (const uint4*)g_W1T;
        uint4* dst = (uint4*)(smem + OFF_W);
        #pragma unroll
        for (int i = 0; i < 8; ++i)
            dst[tid + 256 * i] = src[tid + 256 * i];
    }
    if (tid < HDIM) {
        ((float*)(smem + OFF_SB1))[tid] = b1[tid];
        ((float*)(smem + OFF_SW2))[tid] = W2[tid];
    }

    {
        int c0 = lid * 4;
        uint32_t colpart = (uint32_t)(((c0 >> 6) << 4) * 1024 + (c0 & 63) * 2);
        #pragma unroll 4
        for (int i = 0; i < 16; ++i) {
            int t = wid * 16 + i;
            int op = base + t;
            int m = 0, j = 0;
            if (op < n) { m = m_ids[op]; j = job_idx[op]; }
            uint2 ua = *(const uint2*)(g_Ah + m * HDIM + c0);
            uint2 ub = *(const uint2*)(g_Bh + j * HDIM + c0);
            float2 a0 = __half22float2(*(const half2*)&ua.x);
            float2 a1 = __half22float2(*(const half2*)&ua.y);
            float2 b0f = __half22float2(*(const half2*)&ub.x);
            float2 b1f = __half22float2(*(const half2*)&ub.y);
            float v0 = fmaxf(a0.x + b0f.x, 0.0f);
            float v1 = fmaxf(a0.y + b0f.y, 0.0f);
            float v2 = fmaxf(a1.x + b1f.x, 0.0f);
            float v3 = fmaxf(a1.y + b1f.y, 0.0f);
            half2 r0 = __floats2half2_rn(v0, v1);
            half2 r1 = __floats2half2_rn(v2, v3);
            uint32_t off = colpart + (uint32_t)(((t >> 3) << 10) + (t & 7) * 128);
            uint32_t sw = off ^ ((off >> 3) & 0x70);
            uint2 pv;
            pv.x = *(const uint32_t*)&r0;
            pv.y = *(const uint32_t*)&r1;
            *(uint2*)(smem + OFF_A + sw) = pv;
        }
    }
    __syncthreads();

    float d[16][4];
    #pragma unroll
    for (int nc = 0; nc < 16; ++nc)
        #pragma unroll
        for (int q = 0; q < 4; ++q) d[nc][q] = 0.0f;

    int arow = wid * 16 + (lid & 15);
    int acolh = (lid >> 4) * 8;
    int brow_in = ((lid >> 4) << 3) + (lid & 7);
    int bcol = ((lid >> 3) & 1) * 8;

    // ---- software-pipelined mainloop (same frag mapping as R7) ----
    {
        uint32_t a_cur[4], a_nxt[4], b_cur[4], b_nxt[4];
        ldsm4(a_cur, sb + OFF_A + tile_off(arow, 0 * 16 + acolh));
        ldsm4(b_cur, sb + OFF_W + tile_off(0 * 16 + brow_in, 0 * 16 + bcol));
        #pragma unroll
        for (int kc = 0; kc < 8; ++kc) {
            int kbase = kc * 16;
            #pragma unroll
            for (int np = 0; np < 8; ++np) {
                if (np < 7) {
                    ldsm4(b_nxt, sb + OFF_W +
                          tile_off((np + 1) * 16 + brow_in, kbase + bcol));
                } else if (kc < 7) {
                    ldsm4(b_nxt, sb + OFF_W +
                          tile_off(0 * 16 + brow_in, (kc + 1) * 16 + bcol));
                }
                if (np == 0 && kc < 7) {
                    ldsm4(a_nxt, sb + OFF_A +
                          tile_off(arow, (kc + 1) * 16 + acolh));
                }
                mma_f16(d[2 * np],     a_cur, b_cur[0], b_cur[1]);
                mma_f16(d[2 * np + 1], a_cur, b_cur[2], b_cur[3]);
                #pragma unroll
                for (int q = 0; q < 4; ++q) b_cur[q] = b_nxt[q];
            }
            #pragma unroll
            for (int q = 0; q < 4; ++q) a_cur[q] = a_nxt[q];
        }
    }

    {
        const float* sb1 = (const float*)(smem + OFF_SB1);
        const float* sw2 = (const float*)(smem + OFF_SW2);
        int g = lid >> 2;
        int t4 = lid & 3;
        float s0 = 0.0f, s1 = 0.0f;
        #pragma unroll
        for (int nc = 0; nc < 16; ++nc) {
            int c0 = nc * 8 + 2 * t4;
            float bb0 = sb1[c0], bb1 = sb1[c0 + 1];
            float w0 = sw2[c0], w1 = sw2[c0 + 1];
            s0 = fmaf(fmaxf(d[nc][0] + bb0, 0.0f), w0, s0);
            s0 = fmaf(fmaxf(d[nc][1] + bb1, 0.0f), w1, s0);
            s1 = fmaf(fmaxf(d[nc][2] + bb0, 0.0f), w0, s1);
            s1 = fmaf(fmaxf(d[nc][3] + bb1, 0.0f), w1, s1);
        }
        unsigned mask = 0xffffffffu;
        s0 += __shfl_xor_sync(mask, s0, 1);
        s0 += __shfl_xor_sync(mask, s0, 2);
        s1 += __shfl_xor_sync(mask, s1, 1);
        s1 += __shfl_xor_sync(mask, s1, 2);
        if (t4 == 0) {
            float bias = b2[0];
            int op0 = base + wid * 16 + g;
            int op1 = op0 + 8;
            if (op0 < n) g_scores[op0] = s0 + bias;
            if (op1 < n) g_scores[op1] = s1 + bias;
        }
    }
}

// ---------------------------------------------------------------------------
// Kernel 3a: per-chunk softmax partials, shuffle-based (R13, proven).
// ---------------------------------------------------------------------------
__global__ void __launch_bounds__(RTH1)
kern_reduce1(int n)
{
    __shared__ float  wv_s[16];
    __shared__ int    wi_s[16];
    __shared__ double wz_s[16];
    __shared__ double ws_s[16];
    __shared__ float  mx_s;
    __shared__ int    idx_s;

    int tid = threadIdx.x;
    int lid = tid & 31;
    int wrp = tid >> 5;
    int b = blockIdx.x;
    int i0 = b * RCHUNK + tid * 4;
    unsigned mask = 0xffffffffu;

    float v[4] = { -INFINITY, -INFINITY, -INFINITY, -INFINITY };
    if (i0 + 3 < n) {
        float4 q = *(const float4*)(g_scores + i0);
        v[0] = q.x; v[1] = q.y; v[2] = q.z; v[3] = q.w;
    } else {
        #pragma unroll
        for (int q = 0; q < 4; ++q)
            if (i0 + q < n) v[q] = g_scores[i0 + q];
    }

    float best = v[0]; int bi = i0;
    #pragma unroll
    for (int q = 1; q < 4; ++q)
        if (v[q] > best) { best = v[q]; bi = i0 + q; }
    if (!(best > -INFINITY)) bi = 0x7fffffff;

    wmerge(best, bi, mask, 16);
    wmerge(best, bi, mask, 8);
    wmerge(best, bi, mask, 4);
    wmerge(best, bi, mask, 2);
    wmerge(best, bi, mask, 1);
    if (lid == 0) { wv_s[wrp] = best; wi_s[wrp] = bi; }
    __syncthreads();

    if (wrp == 0) {
        float vv = (lid < 16) ? wv_s[lid] : -INFINITY;
        int ii = (lid < 16) ? wi_s[lid] : 0x7fffffff;
        wmerge(vv, ii, mask, 8);
        wmerge(vv, ii, mask, 4);
        wmerge(vv, ii, mask, 2);
        wmerge(vv, ii, mask, 1);
        if (lid == 0) { mx_s = vv; idx_s = ii; }
    }
    __syncthreads();
    float mx = mx_s;

    double z = 0.0, s1d = 0.0;
    #pragma unroll
    for (int q = 0; q < 4; ++q) {
        if (v[q] > -INFINITY) {
            float t = v[q] - mx;
            float e = expf(t);
            z += (double)e;
            s1d += (double)t * (double)e;
        }
    }
    #pragma unroll
    for (int off = 16; off > 0; off >>= 1) {
        z   += __shfl_xor_sync(mask, z, off);
        s1d += __shfl_xor_sync(mask, s1d, off);
    }
    if (lid == 0) { wz_s[wrp] = z; ws_s[wrp] = s1d; }
    __syncthreads();

    if (wrp == 0) {
        double zz = (lid < 16) ? wz_s[lid] : 0.0;
        double ssv = (lid < 16) ? ws_s[lid] : 0.0;
        #pragma unroll
        for (int off = 8; off > 0; off >>= 1) {
            zz  += __shfl_xor_sync(mask, zz, off);
            ssv += __shfl_xor_sync(mask, ssv, off);
        }
        if (lid == 0) {
            g_pmax[b] = mx;
            g_pidx[b] = idx_s;
            g_pZ[b]   = zz;
            g_pS1[b]  = ssv;
        }
    }
}

// ---------------------------------------------------------------------------
// Kernel 3b: combine nblk (<=128) partials, shuffle-based (R13, proven).
// ---------------------------------------------------------------------------
__global__ void __launch_bounds__(RTH2)
kern_reduce2(int nblk, float* __restrict__ out)
{
    __shared__ float  wv_s[4];
    __shared__ int    wi_s[4];
    __shared__ double wz_s[4];
    __shared__ double ws_s[4];
    __shared__ float  mx_s;
    __shared__ int    idx_s;

    int tid = threadIdx.x;
    int lid = tid & 31;
    int wrp = tid >> 5;
    unsigned mask = 0xffffffffu;

    float best = (tid < nblk) ? g_pmax[tid] : -INFINITY;
    int bi = (tid < nblk) ? g_pidx[tid] : 0x7fffffff;

    wmerge(best, bi, mask, 16);
    wmerge(best, bi, mask, 8);
    wmerge(best, bi, mask, 4);
    wmerge(best, bi, mask, 2);
    wmerge(best, bi, mask, 1);
    if (lid == 0) { wv_s[wrp] = best; wi_s[wrp] = bi; }
    __syncthreads();

    if (wrp == 0) {
        float vv = (lid < 4) ? wv_s[lid] : -INFINITY;
        int ii = (lid < 4) ? wi_s[lid] : 0x7fffffff;
        wmerge(vv, ii, mask, 2);
        wmerge(vv, ii, mask, 1);
        if (lid == 0) { mx_s = vv; idx_s = ii; }
    }
    __syncthreads();
    float mx = mx_s;

    double z = 0.0, s1 = 0.0;
    if (tid < nblk) {
        double zb = g_pZ[tid];
        if (zb > 0.0) {
            double dd = (double)g_pmax[tid] - (double)mx;
            double w = exp(dd);
            z  = w * zb;
            s1 = w * (g_pS1[tid] + dd * zb);
        }
    }
    #pragma unroll
    for (int off = 16; off > 0; off >>= 1) {
        z  += __shfl_xor_sync(mask, z, off);
        s1 += __shfl_xor_sync(mask, s1, off);
    }
    if (lid == 0) { wz_s[wrp] = z; ws_s[wrp] = s1; }
    __syncthreads();

    if (tid == 0) {
        double Z = wz_s[0] + wz_s[1] + wz_s[2] + wz_s[3];
        double S1 = ws_s[0] + ws_s[1] + ws_s[2] + ws_s[3];
        double logZ = log(Z);
        out[0] = (float)idx_s;
        out[1] = (float)(1.0 / Z);
        out[2] = (float)(-logZ);
        out[3] = (float)(logZ - S1 / Z);
    }
}

// ---------------------------------------------------------------------------
extern "C" void kernel_launch(void* const* d_in, const int* in_sizes, int n_in,
                              void* d_out, int out_size)
{
    const float* x_graph = (const float*)d_in[0];
    const float* x_m     = (const float*)d_in[1];
    const float* x_job   = (const float*)d_in[2];
    const int*   m_ids   = (const int*)  d_in[3];
    const int*   job_idx = (const int*)  d_in[4];
    const float* W0      = (const float*)d_in[5];
    const float* b0      = (const float*)d_in[6];
    const float* W1      = (const float*)d_in[7];
    const float* b1      = (const float*)d_in[8];
    const float* W2      = (const float*)d_in[9];
    const float* b2      = (const float*)d_in[10];

    int n = in_sizes[3];
    int M = in_sizes[1] / HDIM;
    int J = in_sizes[2] / HDIM;
    int tiles = (n + TILE_OPS - 1) / TILE_OPS;
    int rblks = (n + RCHUNK - 1) / RCHUNK;
    int ablocks = (M + 7) / 8;
    int bblocks = (J + 7) / 8;

    cudaFuncSetAttribute(kern_tile, cudaFuncAttributeMaxDynamicSharedMemorySize,
                         SMEM_TILE_TOTAL);

    kern_prep1<<<144, HDIM>>>(x_graph, W0, b0, W1);
    kern_AB8<<<ablocks + bblocks, HDIM>>>(x_m, x_job, W0, M, J, ablocks);
    kern_tile<<<tiles, 256, SMEM_TILE_TOTAL>>>(m_ids, job_idx, b1, W2, b2, n);
    kern_reduce1<<<rblks, RTH1>>>(n);
    kern_reduce2<<<1, RTH2>>>(rblks, (float*)d_out);
}